// round 12
// baseline (speedup 1.0000x reference)
#include <cuda_runtime.h>
#include <cuda_bf16.h>
#include <stdint.h>

#define NNODES 100000
#define H1DIM 128
#define H2DIM 64
#define BN_EPS 1e-5f
#define PAD 136
#define EMAX (1 << 20)
#define NSCAN 391   // ceil(NNODES/256)

// ---------------- scratch ----------------
__device__ int   g_degi[NNODES];
__device__ float g_dinv[NNODES];
__device__ int   g_rowptr[NNODES + 2];
__device__ int   g_cursor[NNODES];
__device__ unsigned long long g_stat[512];   // decoupled-lookback state
__device__ int   g_esrc[EMAX];
__device__ float g_enorm[EMAX];
__device__ float g_h2[(size_t)NNODES * H2DIM];
__device__ float g_bns[H1DIM];
__device__ float g_bnt[H1DIM];
__device__ __align__(16) __nv_bfloat16 g_w1h[128 * 128];  // W1^T hi [n][k]
__device__ __align__(16) __nv_bfloat16 g_w1l[128 * 128];
__device__ __align__(16) __nv_bfloat16 g_w2h[64 * 128];
__device__ __align__(16) __nv_bfloat16 g_w2l[64 * 128];

// ---------------- helpers ----------------
__device__ __forceinline__ void mma_bf16(float* c, const uint32_t* a, uint32_t b0, uint32_t b1) {
    asm volatile("mma.sync.aligned.m16n8k16.row.col.f32.bf16.bf16.f32 "
                 "{%0,%1,%2,%3}, {%4,%5,%6,%7}, {%8,%9}, {%0,%1,%2,%3};"
                 : "+f"(c[0]), "+f"(c[1]), "+f"(c[2]), "+f"(c[3])
                 : "r"(a[0]), "r"(a[1]), "r"(a[2]), "r"(a[3]), "r"(b0), "r"(b1));
}
__device__ __forceinline__ void ldsm_x4(uint32_t& r0, uint32_t& r1, uint32_t& r2, uint32_t& r3,
                                        uint32_t addr) {
    asm volatile("ldmatrix.sync.aligned.m8n8.x4.shared.b16 {%0,%1,%2,%3}, [%4];"
                 : "=r"(r0), "=r"(r1), "=r"(r2), "=r"(r3) : "r"(addr));
}
__device__ __forceinline__ void split1(float v, __nv_bfloat16& hi, __nv_bfloat16& lo) {
    hi = __float2bfloat16_rn(v);
    lo = __float2bfloat16_rn(v - __bfloat162float(hi));
}
__device__ __forceinline__ void split2_packed(float a, float b, uint32_t& hi, uint32_t& lo) {
    __nv_bfloat16 ha, la, hb, lb;
    split1(a, ha, la);
    split1(b, hb, lb);
    hi = (uint32_t)__bfloat16_as_ushort(ha) | ((uint32_t)__bfloat16_as_ushort(hb) << 16);
    lo = (uint32_t)__bfloat16_as_ushort(la) | ((uint32_t)__bfloat16_as_ushort(lb) << 16);
}
// per-block edge-dtype detection (deterministic, no global dependency)
__device__ __forceinline__ int detect_is64(const void* ei) {
    __shared__ int s_is64;
    if (threadIdx.x == 0) s_is64 = 1;
    __syncthreads();
    if (threadIdx.x < 64) {
        long long v = ((const long long*)ei)[threadIdx.x];
        if (v < 0 || v >= (long long)NNODES) atomicAnd(&s_is64, 0);
    }
    __syncthreads();
    return s_is64;
}

// ---------------- kernel 1: detect + degree count + W split + stat reset ----------------
__global__ void deg_wsplit_kernel(const void* ei, int E,
                                  const float* __restrict__ W1,
                                  const float* __restrict__ W2) {
    int is64 = detect_is64(ei);
    int i = blockIdx.x * 256 + threadIdx.x;
    if (i < E) {
        int d = is64 ? (int)((const long long*)ei)[(long long)E + i]
                     : ((const int*)ei)[(long long)E + i];
        atomicAdd(&g_degi[d], 1);
    }
    if (i < 512) g_stat[i] = 0ULL;
    if (i < 128 * 128) {
        int k = i >> 7, n = i & 127;
        __nv_bfloat16 hb, lb;
        split1(W1[k * 128 + n], hb, lb);
        g_w1h[n * 128 + k] = hb;
        g_w1l[n * 128 + k] = lb;
    }
    if (i < 128 * 64) {
        int k = i >> 6, n = i & 63;
        __nv_bfloat16 hb, lb;
        split1(W2[k * 64 + n], hb, lb);
        g_w2h[n * 128 + k] = hb;
        g_w2l[n * 128 + k] = lb;
    }
}

// ---------------- kernel 2: dinv + BN + single-pass scan (decoupled lookback) ----------------
__global__ void __launch_bounds__(256) scan_fused_kernel(int E,
                                  const float* __restrict__ b1,
                                  const float* __restrict__ gamma,
                                  const float* __restrict__ beta,
                                  const float* __restrict__ rmean,
                                  const float* __restrict__ rvar) {
    __shared__ int sm[256];
    __shared__ int s_excl;
    const int bid = blockIdx.x, tid = threadIdx.x;
    int i = bid * 256 + tid;
    int v = 0;
    if (i < NNODES) {
        v = g_degi[i];
        g_degi[i] = 0;                        // reset for next graph replay
        g_dinv[i] = rsqrtf((float)v + 1.0f);
    }
    if (i < H1DIM) {
        float s = gamma[i] * rsqrtf(rvar[i] + BN_EPS);
        g_bns[i] = s;
        g_bnt[i] = (b1[i] - rmean[i]) * s + beta[i];
    }
    sm[tid] = v;
    __syncthreads();
    for (int off = 1; off < 256; off <<= 1) {
        int t = (tid >= off) ? sm[tid - off] : 0;
        __syncthreads();
        sm[tid] += t;
        __syncthreads();
    }
    int incl = sm[tid];
    int agg = sm[255];

    if (tid == 0) {
        long long excl = 0;
        if (bid == 0) {
            *(volatile unsigned long long*)&g_stat[0] =
                (2ULL << 62) | (unsigned long long)agg;
        } else {
            *(volatile unsigned long long*)&g_stat[bid] =
                (1ULL << 62) | (unsigned long long)agg;
            for (int p = bid - 1; p >= 0;) {
                unsigned long long st;
                do { st = *(volatile unsigned long long*)&g_stat[p]; } while ((st >> 62) == 0);
                excl += (long long)(st & 0x3FFFFFFFFFFFFFFFULL);
                if ((st >> 62) == 2ULL) break;
                p--;
            }
            *(volatile unsigned long long*)&g_stat[bid] =
                (2ULL << 62) | (unsigned long long)(excl + agg);
        }
        s_excl = (int)excl;
    }
    __syncthreads();
    int excl = s_excl;
    if (i < NNODES) {
        int r = excl + incl - v;
        g_rowptr[i] = r;
        g_cursor[i] = r;
    }
    if (bid == NSCAN - 1 && tid == 255) {
        g_rowptr[NNODES] = E;
        g_rowptr[NNODES + 1] = E;
    }
}

// ---------------- kernel 3: permute edges into CSR ----------------
__global__ void permute_kernel(const void* __restrict__ ei, int E) {
    int is64 = detect_is64(ei);
    int e = blockIdx.x * 256 + threadIdx.x;
    if (e >= E) return;
    int s, d;
    if (is64) {
        s = (int)((const long long*)ei)[e];
        d = (int)((const long long*)ei)[(long long)E + e];
    } else {
        s = ((const int*)ei)[e];
        d = ((const int*)ei)[(long long)E + e];
    }
    float nm = g_dinv[s] * g_dinv[d];
    int pos = atomicAdd(&g_cursor[d], 1);
    g_esrc[pos] = s;
    g_enorm[pos] = nm;
}

// ---------------- fused: gather(x) -> MMA1 -> BN/ReLU -> MMA2 -> h2 ----------------
// 512 threads = 16 warps, 128-row tiles.
#define SMF_AHI 0
#define SMF_ALO (128 * PAD)
#define SMF_W1H (2 * 128 * PAD)
#define SMF_W1L (3 * 128 * PAD)
#define SMF_W2H (4 * 128 * PAD)
#define SMF_W2L (4 * 128 * PAD + 64 * PAD)
#define SMF_TOTAL ((4 * 128 * PAD + 2 * 64 * PAD) * 2)

__global__ void __launch_bounds__(512) fused_kernel(const float* __restrict__ x) {
    extern __shared__ __nv_bfloat16 sm[];
    const uint32_t sbase = (uint32_t)__cvta_generic_to_shared(sm);
    const int tid = threadIdx.x, wid = tid >> 5, lid = tid & 31;
    const int row0 = blockIdx.x * 128;

    // W copies
    for (int i = tid; i < 128 * 16; i += 512) {
        int r = i >> 4, c = i & 15;
        *(uint4*)&sm[SMF_W1H + r * PAD + c * 8] = ((const uint4*)g_w1h)[r * 16 + c];
        *(uint4*)&sm[SMF_W1L + r * PAD + c * 8] = ((const uint4*)g_w1l)[r * 16 + c];
    }
    for (int i = tid; i < 64 * 16; i += 512) {
        int r = i >> 4, c = i & 15;
        *(uint4*)&sm[SMF_W2H + r * PAD + c * 8] = ((const uint4*)g_w2h)[r * 16 + c];
        *(uint4*)&sm[SMF_W2L + r * PAD + c * 8] = ((const uint4*)g_w2l)[r * 16 + c];
    }

    // ---- gather phase: warp handles 8 local rows as 4 node pairs (unroll-4) ----
    const float4* xr = (const float4*)x;
#pragma unroll 1
    for (int pair = 0; pair < 4; pair++) {
        int rl0 = wid * 8 + pair * 2;
        int n0 = row0 + rl0, n1 = n0 + 1;
        float4 acc0 = make_float4(0.f, 0.f, 0.f, 0.f);
        float4 acc1 = make_float4(0.f, 0.f, 0.f, 0.f);
        int beg0 = 0, end0 = 0, end1 = 0;
        if (n0 < NNODES) {
            beg0 = g_rowptr[n0];
            end0 = g_rowptr[n0 + 1];
            end1 = g_rowptr[n0 + 2];
            float di0 = g_dinv[n0];
            acc0 = xr[(size_t)n0 * 32 + lid];
            acc0.x *= di0 * di0; acc0.y *= di0 * di0;
            acc0.z *= di0 * di0; acc0.w *= di0 * di0;
            if (n1 < NNODES) {
                float di1 = g_dinv[n1];
                acc1 = xr[(size_t)n1 * 32 + lid];
                acc1.x *= di1 * di1; acc1.y *= di1 * di1;
                acc1.z *= di1 * di1; acc1.w *= di1 * di1;
            } else {
                end1 = end0;
            }
        }
        int j = beg0;
        for (; j + 4 <= end1; j += 4) {
            int s0 = g_esrc[j], s1 = g_esrc[j + 1], s2 = g_esrc[j + 2], s3 = g_esrc[j + 3];
            float m0 = g_enorm[j], m1 = g_enorm[j + 1], m2 = g_enorm[j + 2], m3 = g_enorm[j + 3];
            float4 v0 = xr[(size_t)s0 * 32 + lid];
            float4 v1 = xr[(size_t)s1 * 32 + lid];
            float4 v2 = xr[(size_t)s2 * 32 + lid];
            float4 v3 = xr[(size_t)s3 * 32 + lid];
            float4* a0 = (j + 0 < end0) ? &acc0 : &acc1;
            float4* a1 = (j + 1 < end0) ? &acc0 : &acc1;
            float4* a2 = (j + 2 < end0) ? &acc0 : &acc1;
            float4* a3 = (j + 3 < end0) ? &acc0 : &acc1;
            a0->x += v0.x * m0; a0->y += v0.y * m0; a0->z += v0.z * m0; a0->w += v0.w * m0;
            a1->x += v1.x * m1; a1->y += v1.y * m1; a1->z += v1.z * m1; a1->w += v1.w * m1;
            a2->x += v2.x * m2; a2->y += v2.y * m2; a2->z += v2.z * m2; a2->w += v2.w * m2;
            a3->x += v3.x * m3; a3->y += v3.y * m3; a3->z += v3.z * m3; a3->w += v3.w * m3;
        }
        for (; j < end1; j++) {
            int s0 = g_esrc[j];
            float m0 = g_enorm[j];
            float4 v0 = xr[(size_t)s0 * 32 + lid];
            float4* a = (j < end0) ? &acc0 : &acc1;
            a->x += v0.x * m0; a->y += v0.y * m0; a->z += v0.z * m0; a->w += v0.w * m0;
        }
        uint32_t h0a, l0a, h0b, l0b;
        split2_packed(acc0.x, acc0.y, h0a, l0a);
        split2_packed(acc0.z, acc0.w, h0b, l0b);
        *(uint2*)&sm[SMF_AHI + rl0 * PAD + lid * 4] = make_uint2(h0a, h0b);
        *(uint2*)&sm[SMF_ALO + rl0 * PAD + lid * 4] = make_uint2(l0a, l0b);
        uint32_t h1a, l1a, h1b, l1b;
        split2_packed(acc1.x, acc1.y, h1a, l1a);
        split2_packed(acc1.z, acc1.w, h1b, l1b);
        *(uint2*)&sm[SMF_AHI + (rl0 + 1) * PAD + lid * 4] = make_uint2(h1a, h1b);
        *(uint2*)&sm[SMF_ALO + (rl0 + 1) * PAD + lid * 4] = make_uint2(l1a, l1b);
    }
    __syncthreads();

    // warp grid 4x4
    const int wr = wid >> 2, wc = wid & 3;
    const int g = lid >> 2, tg = lid & 3;
    const int ar0 = wr * 32;

    const int m4 = lid >> 3;
    const int arow = (m4 & 1) * 8 + (lid & 7);
    const int acol = (m4 >> 1) * 8;
    const uint32_t offA0 = (uint32_t)(((ar0 + arow) * PAD + acol) * 2);
    const uint32_t offA1 = (uint32_t)(((ar0 + 16 + arow) * PAD + acol) * 2);
    const int brow = (m4 >> 1) * 8 + (lid & 7);
    const int bcol = (m4 & 1) * 8;

    // ---------- MMA1: warp tile 32x32 at (ar0, nc1) ----------
    {
        const int nc1 = wc * 32;
        uint32_t offB[2];
#pragma unroll
        for (int bi = 0; bi < 2; bi++)
            offB[bi] = (uint32_t)(((nc1 + bi * 16 + brow) * PAD + bcol) * 2);

        float acc[2][4][4];
#pragma unroll
        for (int mi = 0; mi < 2; mi++)
#pragma unroll
            for (int ni = 0; ni < 4; ni++)
#pragma unroll
                for (int j = 0; j < 4; j++) acc[mi][ni][j] = 0.f;

#pragma unroll 1
        for (int pass = 0; pass < 3; pass++) {
            uint32_t abase = sbase + 2 * ((pass == 2) ? SMF_ALO : SMF_AHI);
            uint32_t bbase = sbase + 2 * ((pass == 1) ? SMF_W1L : SMF_W1H);
#pragma unroll 1
            for (int ks = 0; ks < 8; ks++) {
                uint32_t kb = (uint32_t)ks * 32;
                uint32_t a0[4], a1[4];
                ldsm_x4(a0[0], a0[1], a0[2], a0[3], abase + offA0 + kb);
                ldsm_x4(a1[0], a1[1], a1[2], a1[3], abase + offA1 + kb);
#pragma unroll
                for (int bi = 0; bi < 2; bi++) {
                    uint32_t b0, b1, b2, b3;
                    ldsm_x4(b0, b1, b2, b3, bbase + offB[bi] + kb);
                    mma_bf16(acc[0][2 * bi], a0, b0, b1);
                    mma_bf16(acc[0][2 * bi + 1], a0, b2, b3);
                    mma_bf16(acc[1][2 * bi], a1, b0, b1);
                    mma_bf16(acc[1][2 * bi + 1], a1, b2, b3);
                }
            }
        }

        __syncthreads();

        // BN + ReLU + split -> overwrite A planes
#pragma unroll
        for (int mi = 0; mi < 2; mi++)
#pragma unroll
            for (int h = 0; h < 2; h++) {
                int rl = ar0 + mi * 16 + h * 8 + g;
#pragma unroll
                for (int ni = 0; ni < 4; ni++) {
                    int c = nc1 + ni * 8 + tg * 2;
                    float2 sc = *(const float2*)&g_bns[c];
                    float2 tc = *(const float2*)&g_bnt[c];
                    float v0 = fmaxf(acc[mi][ni][h * 2] * sc.x + tc.x, 0.f);
                    float v1 = fmaxf(acc[mi][ni][h * 2 + 1] * sc.y + tc.y, 0.f);
                    uint32_t hi, lo;
                    split2_packed(v0, v1, hi, lo);
                    *(uint32_t*)&sm[SMF_AHI + rl * PAD + c] = hi;
                    *(uint32_t*)&sm[SMF_ALO + rl * PAD + c] = lo;
                }
            }
    }
    __syncthreads();

    // ---------- MMA2: warp tile 32x16 at (ar0, nc2) ----------
    {
        const int nc2 = wc * 16;
        const uint32_t offB0 = (uint32_t)(((nc2 + brow) * PAD + bcol) * 2);

        float acc[2][2][4];
#pragma unroll
        for (int mi = 0; mi < 2; mi++)
#pragma unroll
            for (int ni = 0; ni < 2; ni++)
#pragma unroll
                for (int j = 0; j < 4; j++) acc[mi][ni][j] = 0.f;

#pragma unroll 1
        for (int pass = 0; pass < 3; pass++) {
            uint32_t abase = sbase + 2 * ((pass == 2) ? SMF_ALO : SMF_AHI);
            uint32_t bbase = sbase + 2 * ((pass == 1) ? SMF_W2L : SMF_W2H);
#pragma unroll 1
            for (int ks = 0; ks < 8; ks++) {
                uint32_t kb = (uint32_t)ks * 32;
                uint32_t a0[4], a1[4];
                ldsm_x4(a0[0], a0[1], a0[2], a0[3], abase + offA0 + kb);
                ldsm_x4(a1[0], a1[1], a1[2], a1[3], abase + offA1 + kb);
                uint32_t b0, b1, b2, b3;
                ldsm_x4(b0, b1, b2, b3, bbase + offB0 + kb);
                mma_bf16(acc[0][0], a0, b0, b1);
                mma_bf16(acc[0][1], a0, b2, b3);
                mma_bf16(acc[1][0], a1, b0, b1);
                mma_bf16(acc[1][1], a1, b2, b3);
            }
        }

#pragma unroll
        for (int mi = 0; mi < 2; mi++)
#pragma unroll
            for (int h = 0; h < 2; h++) {
                int r = row0 + ar0 + mi * 16 + g + h * 8;
                if (r < NNODES) {
#pragma unroll
                    for (int ni = 0; ni < 2; ni++) {
                        int c = nc2 + ni * 8 + tg * 2;
                        *(float2*)&g_h2[(size_t)r * 64 + c] =
                            make_float2(acc[mi][ni][h * 2], acc[mi][ni][h * 2 + 1]);
                    }
                }
            }
    }
}

// ---------------- agg2: half-warp per node (unroll-4) ----------------
__global__ void __launch_bounds__(256) agg2_kernel(const float* __restrict__ b2,
                                                   float* __restrict__ out) {
    int t = blockIdx.x * blockDim.x + threadIdx.x;
    int hw = t >> 4;
    int sub = t & 15;
    if (hw >= NNODES) return;
    int beg = g_rowptr[hw], end = g_rowptr[hw + 1];
    float di = g_dinv[hw];
    float d2 = di * di;
    const float4* h2 = (const float4*)g_h2;
    float4 acc = h2[(size_t)hw * 16 + sub];
    acc.x *= d2; acc.y *= d2; acc.z *= d2; acc.w *= d2;
    int j = beg;
    for (; j + 4 <= end; j += 4) {
        int s0 = g_esrc[j], s1 = g_esrc[j + 1], s2 = g_esrc[j + 2], s3 = g_esrc[j + 3];
        float n0 = g_enorm[j], n1 = g_enorm[j + 1], n2 = g_enorm[j + 2], n3 = g_enorm[j + 3];
        float4 v0 = h2[(size_t)s0 * 16 + sub];
        float4 v1 = h2[(size_t)s1 * 16 + sub];
        float4 v2 = h2[(size_t)s2 * 16 + sub];
        float4 v3 = h2[(size_t)s3 * 16 + sub];
        acc.x += v0.x * n0 + v1.x * n1 + v2.x * n2 + v3.x * n3;
        acc.y += v0.y * n0 + v1.y * n1 + v2.y * n2 + v3.y * n3;
        acc.z += v0.z * n0 + v1.z * n1 + v2.z * n2 + v3.z * n3;
        acc.w += v0.w * n0 + v1.w * n1 + v2.w * n2 + v3.w * n3;
    }
    for (; j < end; j++) {
        int s0 = g_esrc[j];
        float n0 = g_enorm[j];
        float4 v0 = h2[(size_t)s0 * 16 + sub];
        acc.x += v0.x * n0; acc.y += v0.y * n0; acc.z += v0.z * n0; acc.w += v0.w * n0;
    }
    float4 bv = ((const float4*)b2)[sub];
    ((float4*)out)[(size_t)hw * 16 + sub] =
        make_float4(acc.x + bv.x, acc.y + bv.y, acc.z + bv.z, acc.w + bv.w);
}

// ---------------- launch ----------------
extern "C" void kernel_launch(void* const* d_in, const int* in_sizes, int n_in,
                              void* d_out, int out_size) {
    const float* x     = (const float*)d_in[0];
    const void*  ei    = d_in[1];
    const float* W1    = (const float*)d_in[2];
    const float* b1    = (const float*)d_in[3];
    const float* gamma = (const float*)d_in[4];
    const float* beta  = (const float*)d_in[5];
    const float* rmean = (const float*)d_in[6];
    const float* rvar  = (const float*)d_in[7];
    const float* W2    = (const float*)d_in[8];
    const float* b2    = (const float*)d_in[9];
    float* out = (float*)d_out;

    const int E = in_sizes[1] / 2;

    cudaFuncSetAttribute(fused_kernel, cudaFuncAttributeMaxDynamicSharedMemorySize, SMF_TOTAL);

    int eblk = (E + 255) / 256;
    deg_wsplit_kernel<<<eblk, 256>>>(ei, E, W1, W2);
    scan_fused_kernel<<<NSCAN, 256>>>(E, b1, gamma, beta, rmean, rvar);
    permute_kernel<<<eblk, 256>>>(ei, E);

    int gblk = (NNODES + 127) / 128;  // 782
    fused_kernel<<<gblk, 512, SMF_TOTAL>>>(x);

    {
        long long th = (long long)NNODES * 16;
        agg2_kernel<<<(int)((th + 255) / 256), 256>>>(b2, out);
    }
}

// round 13
// speedup vs baseline: 1.1701x; 1.1701x over previous
#include <cuda_runtime.h>
#include <cuda_bf16.h>
#include <stdint.h>

#define NNODES 100000
#define H1DIM 128
#define H2DIM 64
#define BN_EPS 1e-5f
#define PAD 136
#define EMAX (1 << 20)
#define NSCAN 391   // ceil(NNODES/256)

// ---------------- scratch ----------------
__device__ int   g_degi[NNODES];
__device__ float g_dinv[NNODES];
__device__ int   g_rowptr[NNODES + 2];
__device__ int   g_cursor[NNODES];
__device__ unsigned long long g_stat[512];   // decoupled-lookback state
__device__ int   g_esrc[EMAX];
__device__ float g_enorm[EMAX];
__device__ float g_h2[(size_t)NNODES * H2DIM];
__device__ float g_bns[H1DIM];
__device__ float g_bnt[H1DIM];
// fragment-packed weights: [ntile][ks][lane] -> {b0, b1} (uint2)
__device__ __align__(16) uint2 g_w1hp[16 * 8 * 32];
__device__ __align__(16) uint2 g_w1lp[16 * 8 * 32];
__device__ __align__(16) uint2 g_w2hp[8 * 8 * 32];
__device__ __align__(16) uint2 g_w2lp[8 * 8 * 32];

// ---------------- helpers ----------------
__device__ __forceinline__ void mma_bf16(float* c, const uint32_t* a, uint32_t b0, uint32_t b1) {
    asm volatile("mma.sync.aligned.m16n8k16.row.col.f32.bf16.bf16.f32 "
                 "{%0,%1,%2,%3}, {%4,%5,%6,%7}, {%8,%9}, {%0,%1,%2,%3};"
                 : "+f"(c[0]), "+f"(c[1]), "+f"(c[2]), "+f"(c[3])
                 : "r"(a[0]), "r"(a[1]), "r"(a[2]), "r"(a[3]), "r"(b0), "r"(b1));
}
__device__ __forceinline__ void ldsm_x4(uint32_t& r0, uint32_t& r1, uint32_t& r2, uint32_t& r3,
                                        uint32_t addr) {
    asm volatile("ldmatrix.sync.aligned.m8n8.x4.shared.b16 {%0,%1,%2,%3}, [%4];"
                 : "=r"(r0), "=r"(r1), "=r"(r2), "=r"(r3) : "r"(addr));
}
__device__ __forceinline__ void split1(float v, __nv_bfloat16& hi, __nv_bfloat16& lo) {
    hi = __float2bfloat16_rn(v);
    lo = __float2bfloat16_rn(v - __bfloat162float(hi));
}
__device__ __forceinline__ uint32_t pack2(__nv_bfloat16 a, __nv_bfloat16 b) {
    return (uint32_t)__bfloat16_as_ushort(a) | ((uint32_t)__bfloat16_as_ushort(b) << 16);
}
__device__ __forceinline__ void split2_packed(float a, float b, uint32_t& hi, uint32_t& lo) {
    __nv_bfloat16 ha, la, hb, lb;
    split1(a, ha, la);
    split1(b, hb, lb);
    hi = pack2(ha, hb);
    lo = pack2(la, lb);
}
__device__ __forceinline__ int detect_is64(const void* ei) {
    __shared__ int s_is64;
    if (threadIdx.x == 0) s_is64 = 1;
    __syncthreads();
    if (threadIdx.x < 64) {
        long long v = ((const long long*)ei)[threadIdx.x];
        if (v < 0 || v >= (long long)NNODES) atomicAnd(&s_is64, 0);
    }
    __syncthreads();
    return s_is64;
}

// ---------------- kernel 1: detect + degree count + W fragment-pack + stat reset ----------------
__global__ void deg_wsplit_kernel(const void* ei, int E,
                                  const float* __restrict__ W1,
                                  const float* __restrict__ W2) {
    int is64 = detect_is64(ei);
    int i = blockIdx.x * 256 + threadIdx.x;
    if (i < E) {
        int d = is64 ? (int)((const long long*)ei)[(long long)E + i]
                     : ((const int*)ei)[(long long)E + i];
        atomicAdd(&g_degi[d], 1);
    }
    if (i < 512) g_stat[i] = 0ULL;
    // W1 fragment packing: 16 ntiles x 8 ks x 32 lanes
    if (i < 16 * 8 * 32) {
        int lane = i & 31, ks = (i >> 5) & 7, nt = i >> 8;
        int g = lane >> 2, tg = lane & 3;
        int n = nt * 8 + g;
        int k = ks * 16 + tg * 2;
        __nv_bfloat16 h0, l0, h1, l1, h2, l2, h3, l3;
        split1(W1[(k + 0) * 128 + n], h0, l0);
        split1(W1[(k + 1) * 128 + n], h1, l1);
        split1(W1[(k + 8) * 128 + n], h2, l2);
        split1(W1[(k + 9) * 128 + n], h3, l3);
        g_w1hp[i] = make_uint2(pack2(h0, h1), pack2(h2, h3));
        g_w1lp[i] = make_uint2(pack2(l0, l1), pack2(l2, l3));
    }
    // W2 fragment packing: 8 ntiles x 8 ks x 32 lanes
    if (i < 8 * 8 * 32) {
        int lane = i & 31, ks = (i >> 5) & 7, nt = i >> 8;
        int g = lane >> 2, tg = lane & 3;
        int n = nt * 8 + g;
        int k = ks * 16 + tg * 2;
        __nv_bfloat16 h0, l0, h1, l1, h2, l2, h3, l3;
        split1(W2[(k + 0) * 64 + n], h0, l0);
        split1(W2[(k + 1) * 64 + n], h1, l1);
        split1(W2[(k + 8) * 64 + n], h2, l2);
        split1(W2[(k + 9) * 64 + n], h3, l3);
        g_w2hp[i] = make_uint2(pack2(h0, h1), pack2(h2, h3));
        g_w2lp[i] = make_uint2(pack2(l0, l1), pack2(l2, l3));
    }
}

// ---------------- kernel 2: dinv + BN + single-pass scan (decoupled lookback) ----------------
__global__ void __launch_bounds__(256) scan_fused_kernel(int E,
                                  const float* __restrict__ b1,
                                  const float* __restrict__ gamma,
                                  const float* __restrict__ beta,
                                  const float* __restrict__ rmean,
                                  const float* __restrict__ rvar) {
    __shared__ int sm[256];
    __shared__ int s_excl;
    const int bid = blockIdx.x, tid = threadIdx.x;
    int i = bid * 256 + tid;
    int v = 0;
    if (i < NNODES) {
        v = g_degi[i];
        g_degi[i] = 0;
        g_dinv[i] = rsqrtf((float)v + 1.0f);
    }
    if (i < H1DIM) {
        float s = gamma[i] * rsqrtf(rvar[i] + BN_EPS);
        g_bns[i] = s;
        g_bnt[i] = (b1[i] - rmean[i]) * s + beta[i];
    }
    sm[tid] = v;
    __syncthreads();
    for (int off = 1; off < 256; off <<= 1) {
        int t = (tid >= off) ? sm[tid - off] : 0;
        __syncthreads();
        sm[tid] += t;
        __syncthreads();
    }
    int incl = sm[tid];
    int agg = sm[255];

    if (tid == 0) {
        long long excl = 0;
        if (bid == 0) {
            *(volatile unsigned long long*)&g_stat[0] =
                (2ULL << 62) | (unsigned long long)agg;
        } else {
            *(volatile unsigned long long*)&g_stat[bid] =
                (1ULL << 62) | (unsigned long long)agg;
            for (int p = bid - 1; p >= 0;) {
                unsigned long long st;
                do { st = *(volatile unsigned long long*)&g_stat[p]; } while ((st >> 62) == 0);
                excl += (long long)(st & 0x3FFFFFFFFFFFFFFFULL);
                if ((st >> 62) == 2ULL) break;
                p--;
            }
            *(volatile unsigned long long*)&g_stat[bid] =
                (2ULL << 62) | (unsigned long long)(excl + agg);
        }
        s_excl = (int)excl;
    }
    __syncthreads();
    int excl = s_excl;
    if (i < NNODES) {
        int r = excl + incl - v;
        g_rowptr[i] = r;
        g_cursor[i] = r;
    }
    if (bid == NSCAN - 1 && tid == 255) {
        g_rowptr[NNODES] = E;
        g_rowptr[NNODES + 1] = E;
    }
}

// ---------------- kernel 3: permute edges into CSR ----------------
__global__ void permute_kernel(const void* __restrict__ ei, int E) {
    int is64 = detect_is64(ei);
    int e = blockIdx.x * 256 + threadIdx.x;
    if (e >= E) return;
    int s, d;
    if (is64) {
        s = (int)((const long long*)ei)[e];
        d = (int)((const long long*)ei)[(long long)E + e];
    } else {
        s = ((const int*)ei)[e];
        d = ((const int*)ei)[(long long)E + e];
    }
    float nm = g_dinv[s] * g_dinv[d];
    int pos = atomicAdd(&g_cursor[d], 1);
    g_esrc[pos] = s;
    g_enorm[pos] = nm;
}

// ---------------- fused: gather(x) -> MMA1 -> BN/ReLU -> MMA2 -> h2 ----------------
// 512 threads = 16 warps, 128-row tiles, 2 CTAs/SM.
// smem (bf16 elems): A hi, A lo (128*PAD each), then W1h packed (4096 uint2 = 16384 elems)
#define SMF_AHI 0
#define SMF_ALO (128 * PAD)
#define SMF_W1P (2 * 128 * PAD)
#define SMF_TOTAL ((2 * 128 * PAD + 16384) * 2)   // 102,400 B

__global__ void __launch_bounds__(512, 2) fused_kernel(const float* __restrict__ x) {
    extern __shared__ __nv_bfloat16 sm[];
    const uint32_t sbase = (uint32_t)__cvta_generic_to_shared(sm);
    const int tid = threadIdx.x, wid = tid >> 5, lid = tid & 31;
    const int row0 = blockIdx.x * 128;

    // W1h packed copy (2048 uint4)
    for (int i = tid; i < 2048; i += 512)
        ((uint4*)(sm + SMF_W1P))[i] = ((const uint4*)g_w1hp)[i];

    // ---- gather phase: warp handles 8 local rows as 4 node pairs (unroll-4) ----
    const float4* xr = (const float4*)x;
#pragma unroll 1
    for (int pair = 0; pair < 4; pair++) {
        int rl0 = wid * 8 + pair * 2;
        int n0 = row0 + rl0, n1 = n0 + 1;
        float4 acc0 = make_float4(0.f, 0.f, 0.f, 0.f);
        float4 acc1 = make_float4(0.f, 0.f, 0.f, 0.f);
        int beg0 = 0, end0 = 0, end1 = 0;
        if (n0 < NNODES) {
            beg0 = g_rowptr[n0];
            end0 = g_rowptr[n0 + 1];
            end1 = g_rowptr[n0 + 2];
            float di0 = g_dinv[n0];
            acc0 = xr[(size_t)n0 * 32 + lid];
            acc0.x *= di0 * di0; acc0.y *= di0 * di0;
            acc0.z *= di0 * di0; acc0.w *= di0 * di0;
            if (n1 < NNODES) {
                float di1 = g_dinv[n1];
                acc1 = xr[(size_t)n1 * 32 + lid];
                acc1.x *= di1 * di1; acc1.y *= di1 * di1;
                acc1.z *= di1 * di1; acc1.w *= di1 * di1;
            } else {
                end1 = end0;
            }
        }
        int j = beg0;
        for (; j + 4 <= end1; j += 4) {
            int s0 = g_esrc[j], s1 = g_esrc[j + 1], s2 = g_esrc[j + 2], s3 = g_esrc[j + 3];
            float m0 = g_enorm[j], m1 = g_enorm[j + 1], m2 = g_enorm[j + 2], m3 = g_enorm[j + 3];
            float4 v0 = xr[(size_t)s0 * 32 + lid];
            float4 v1 = xr[(size_t)s1 * 32 + lid];
            float4 v2 = xr[(size_t)s2 * 32 + lid];
            float4 v3 = xr[(size_t)s3 * 32 + lid];
            float4* a0 = (j + 0 < end0) ? &acc0 : &acc1;
            float4* a1 = (j + 1 < end0) ? &acc0 : &acc1;
            float4* a2 = (j + 2 < end0) ? &acc0 : &acc1;
            float4* a3 = (j + 3 < end0) ? &acc0 : &acc1;
            a0->x += v0.x * m0; a0->y += v0.y * m0; a0->z += v0.z * m0; a0->w += v0.w * m0;
            a1->x += v1.x * m1; a1->y += v1.y * m1; a1->z += v1.z * m1; a1->w += v1.w * m1;
            a2->x += v2.x * m2; a2->y += v2.y * m2; a2->z += v2.z * m2; a2->w += v2.w * m2;
            a3->x += v3.x * m3; a3->y += v3.y * m3; a3->z += v3.z * m3; a3->w += v3.w * m3;
        }
        for (; j < end1; j++) {
            int s0 = g_esrc[j];
            float m0 = g_enorm[j];
            float4 v0 = xr[(size_t)s0 * 32 + lid];
            float4* a = (j < end0) ? &acc0 : &acc1;
            a->x += v0.x * m0; a->y += v0.y * m0; a->z += v0.z * m0; a->w += v0.w * m0;
        }
        uint32_t h0a, l0a, h0b, l0b;
        split2_packed(acc0.x, acc0.y, h0a, l0a);
        split2_packed(acc0.z, acc0.w, h0b, l0b);
        *(uint2*)&sm[SMF_AHI + rl0 * PAD + lid * 4] = make_uint2(h0a, h0b);
        *(uint2*)&sm[SMF_ALO + rl0 * PAD + lid * 4] = make_uint2(l0a, l0b);
        uint32_t h1a, l1a, h1b, l1b;
        split2_packed(acc1.x, acc1.y, h1a, l1a);
        split2_packed(acc1.z, acc1.w, h1b, l1b);
        *(uint2*)&sm[SMF_AHI + (rl0 + 1) * PAD + lid * 4] = make_uint2(h1a, h1b);
        *(uint2*)&sm[SMF_ALO + (rl0 + 1) * PAD + lid * 4] = make_uint2(l1a, l1b);
    }
    __syncthreads();

    // warp grid 4x4
    const int wr = wid >> 2, wc = wid & 3;
    const int g = lid >> 2, tg = lid & 3;
    const int ar0 = wr * 32;

    const int m4 = lid >> 3;
    const int arow = (m4 & 1) * 8 + (lid & 7);
    const int acol = (m4 >> 1) * 8;
    const uint32_t offA0 = (uint32_t)(((ar0 + arow) * PAD + acol) * 2);
    const uint32_t offA1 = (uint32_t)(((ar0 + 16 + arow) * PAD + acol) * 2);

    const uint2* sw1p = (const uint2*)(sm + SMF_W1P);

    // ---------- MMA1: warp tile 32x32 at (ar0, nc1) ----------
    {
        const int nc1 = wc * 32;
        float acc[2][4][4];
#pragma unroll
        for (int mi = 0; mi < 2; mi++)
#pragma unroll
            for (int ni = 0; ni < 4; ni++)
#pragma unroll
                for (int j = 0; j < 4; j++) acc[mi][ni][j] = 0.f;

#pragma unroll 1
        for (int pass = 0; pass < 3; pass++) {
            uint32_t abase = sbase + 2 * ((pass == 2) ? SMF_ALO : SMF_AHI);
            const bool blo = (pass == 1);
#pragma unroll 1
            for (int ks = 0; ks < 8; ks++) {
                uint32_t kb = (uint32_t)ks * 32;
                uint32_t a0[4], a1[4];
                ldsm_x4(a0[0], a0[1], a0[2], a0[3], abase + offA0 + kb);
                ldsm_x4(a1[0], a1[1], a1[2], a1[3], abase + offA1 + kb);
#pragma unroll
                for (int ni = 0; ni < 4; ni++) {
                    int idx = ((wc * 4 + ni) * 8 + ks) * 32 + lid;
                    uint2 bf = blo ? g_w1lp[idx] : sw1p[idx];
                    mma_bf16(acc[0][ni], a0, bf.x, bf.y);
                    mma_bf16(acc[1][ni], a1, bf.x, bf.y);
                }
            }
        }

        __syncthreads();

        // BN + ReLU + split -> overwrite A planes
#pragma unroll
        for (int mi = 0; mi < 2; mi++)
#pragma unroll
            for (int h = 0; h < 2; h++) {
                int rl = ar0 + mi * 16 + h * 8 + g;
#pragma unroll
                for (int ni = 0; ni < 4; ni++) {
                    int c = nc1 + ni * 8 + tg * 2;
                    float2 sc = *(const float2*)&g_bns[c];
                    float2 tc = *(const float2*)&g_bnt[c];
                    float v0 = fmaxf(acc[mi][ni][h * 2] * sc.x + tc.x, 0.f);
                    float v1 = fmaxf(acc[mi][ni][h * 2 + 1] * sc.y + tc.y, 0.f);
                    uint32_t hi, lo;
                    split2_packed(v0, v1, hi, lo);
                    *(uint32_t*)&sm[SMF_AHI + rl * PAD + c] = hi;
                    *(uint32_t*)&sm[SMF_ALO + rl * PAD + c] = lo;
                }
            }
    }
    __syncthreads();

    // ---------- MMA2: warp tile 32x16 at (ar0, nc2) ----------
    {
        const int nc2 = wc * 16;
        float acc[2][2][4];
#pragma unroll
        for (int mi = 0; mi < 2; mi++)
#pragma unroll
            for (int ni = 0; ni < 2; ni++)
#pragma unroll
                for (int j = 0; j < 4; j++) acc[mi][ni][j] = 0.f;

#pragma unroll 1
        for (int pass = 0; pass < 3; pass++) {
            uint32_t abase = sbase + 2 * ((pass == 2) ? SMF_ALO : SMF_AHI);
            const uint2* wp = (pass == 1) ? g_w2lp : g_w2hp;
#pragma unroll 1
            for (int ks = 0; ks < 8; ks++) {
                uint32_t kb = (uint32_t)ks * 32;
                uint32_t a0[4], a1[4];
                ldsm_x4(a0[0], a0[1], a0[2], a0[3], abase + offA0 + kb);
                ldsm_x4(a1[0], a1[1], a1[2], a1[3], abase + offA1 + kb);
#pragma unroll
                for (int ni = 0; ni < 2; ni++) {
                    int idx = ((wc * 2 + ni) * 8 + ks) * 32 + lid;
                    uint2 bf = wp[idx];
                    mma_bf16(acc[0][ni], a0, bf.x, bf.y);
                    mma_bf16(acc[1][ni], a1, bf.x, bf.y);
                }
            }
        }

#pragma unroll
        for (int mi = 0; mi < 2; mi++)
#pragma unroll
            for (int h = 0; h < 2; h++) {
                int r = row0 + ar0 + mi * 16 + g + h * 8;
                if (r < NNODES) {
#pragma unroll
                    for (int ni = 0; ni < 2; ni++) {
                        int c = nc2 + ni * 8 + tg * 2;
                        *(float2*)&g_h2[(size_t)r * 64 + c] =
                            make_float2(acc[mi][ni][h * 2], acc[mi][ni][h * 2 + 1]);
                    }
                }
            }
    }
}

// ---------------- agg2: half-warp per node (unroll-4) ----------------
__global__ void __launch_bounds__(256) agg2_kernel(const float* __restrict__ b2,
                                                   float* __restrict__ out) {
    int t = blockIdx.x * blockDim.x + threadIdx.x;
    int hw = t >> 4;
    int sub = t & 15;
    if (hw >= NNODES) return;
    int beg = g_rowptr[hw], end = g_rowptr[hw + 1];
    float di = g_dinv[hw];
    float d2 = di * di;
    const float4* h2 = (const float4*)g_h2;
    float4 acc = h2[(size_t)hw * 16 + sub];
    acc.x *= d2; acc.y *= d2; acc.z *= d2; acc.w *= d2;
    int j = beg;
    for (; j + 4 <= end; j += 4) {
        int s0 = g_esrc[j], s1 = g_esrc[j + 1], s2 = g_esrc[j + 2], s3 = g_esrc[j + 3];
        float n0 = g_enorm[j], n1 = g_enorm[j + 1], n2 = g_enorm[j + 2], n3 = g_enorm[j + 3];
        float4 v0 = h2[(size_t)s0 * 16 + sub];
        float4 v1 = h2[(size_t)s1 * 16 + sub];
        float4 v2 = h2[(size_t)s2 * 16 + sub];
        float4 v3 = h2[(size_t)s3 * 16 + sub];
        acc.x += v0.x * n0 + v1.x * n1 + v2.x * n2 + v3.x * n3;
        acc.y += v0.y * n0 + v1.y * n1 + v2.y * n2 + v3.y * n3;
        acc.z += v0.z * n0 + v1.z * n1 + v2.z * n2 + v3.z * n3;
        acc.w += v0.w * n0 + v1.w * n1 + v2.w * n2 + v3.w * n3;
    }
    for (; j < end; j++) {
        int s0 = g_esrc[j];
        float n0 = g_enorm[j];
        float4 v0 = h2[(size_t)s0 * 16 + sub];
        acc.x += v0.x * n0; acc.y += v0.y * n0; acc.z += v0.z * n0; acc.w += v0.w * n0;
    }
    float4 bv = ((const float4*)b2)[sub];
    ((float4*)out)[(size_t)hw * 16 + sub] =
        make_float4(acc.x + bv.x, acc.y + bv.y, acc.z + bv.z, acc.w + bv.w);
}

// ---------------- launch ----------------
extern "C" void kernel_launch(void* const* d_in, const int* in_sizes, int n_in,
                              void* d_out, int out_size) {
    const float* x     = (const float*)d_in[0];
    const void*  ei    = d_in[1];
    const float* W1    = (const float*)d_in[2];
    const float* b1    = (const float*)d_in[3];
    const float* gamma = (const float*)d_in[4];
    const float* beta  = (const float*)d_in[5];
    const float* rmean = (const float*)d_in[6];
    const float* rvar  = (const float*)d_in[7];
    const float* W2    = (const float*)d_in[8];
    const float* b2    = (const float*)d_in[9];
    float* out = (float*)d_out;

    const int E = in_sizes[1] / 2;

    cudaFuncSetAttribute(fused_kernel, cudaFuncAttributeMaxDynamicSharedMemorySize, SMF_TOTAL);

    int eblk = (E + 255) / 256;
    deg_wsplit_kernel<<<eblk, 256>>>(ei, E, W1, W2);
    scan_fused_kernel<<<NSCAN, 256>>>(E, b1, gamma, beta, rmean, rvar);
    permute_kernel<<<eblk, 256>>>(ei, E);

    int gblk = (NNODES + 127) / 128;  // 782
    fused_kernel<<<gblk, 512, SMF_TOTAL>>>(x);

    {
        long long th = (long long)NNODES * 16;
        agg2_kernel<<<(int)((th + 255) / 256), 256>>>(b2, out);
    }
}

// round 14
// speedup vs baseline: 1.3137x; 1.1227x over previous
#include <cuda_runtime.h>
#include <cuda_bf16.h>
#include <stdint.h>

#define NNODES 100000
#define H1DIM 128
#define H2DIM 64
#define BN_EPS 1e-5f
#define PAD 136
#define EMAX (1 << 20)
#define NSCAN 391   // ceil(NNODES/256)

// ---------------- scratch ----------------
__device__ int   g_degi[NNODES];
__device__ float g_dinv[NNODES];
__device__ int   g_rowptr[NNODES + 2];
__device__ int   g_cursor[NNODES];
__device__ unsigned long long g_stat[512];   // decoupled-lookback state
__device__ int   g_esrc[EMAX];
__device__ float g_enorm[EMAX];
__device__ float g_h2[(size_t)NNODES * H2DIM];
__device__ float g_bns[H1DIM];
__device__ float g_bnt[H1DIM];
// fragment-packed weights: [ntile][ks][lane] -> {b0, b1} (uint2)
__device__ __align__(16) uint2 g_w1hp[16 * 8 * 32];
__device__ __align__(16) uint2 g_w1lp[16 * 8 * 32];
__device__ __align__(16) uint2 g_w2hp[8 * 8 * 32];
__device__ __align__(16) uint2 g_w2lp[8 * 8 * 32];

// ---------------- helpers ----------------
__device__ __forceinline__ void mma_bf16(float* c, const uint32_t* a, uint32_t b0, uint32_t b1) {
    asm volatile("mma.sync.aligned.m16n8k16.row.col.f32.bf16.bf16.f32 "
                 "{%0,%1,%2,%3}, {%4,%5,%6,%7}, {%8,%9}, {%0,%1,%2,%3};"
                 : "+f"(c[0]), "+f"(c[1]), "+f"(c[2]), "+f"(c[3])
                 : "r"(a[0]), "r"(a[1]), "r"(a[2]), "r"(a[3]), "r"(b0), "r"(b1));
}
__device__ __forceinline__ void ldsm_x4(uint32_t& r0, uint32_t& r1, uint32_t& r2, uint32_t& r3,
                                        uint32_t addr) {
    asm volatile("ldmatrix.sync.aligned.m8n8.x4.shared.b16 {%0,%1,%2,%3}, [%4];"
                 : "=r"(r0), "=r"(r1), "=r"(r2), "=r"(r3) : "r"(addr));
}
__device__ __forceinline__ void split1(float v, __nv_bfloat16& hi, __nv_bfloat16& lo) {
    hi = __float2bfloat16_rn(v);
    lo = __float2bfloat16_rn(v - __bfloat162float(hi));
}
__device__ __forceinline__ uint32_t pack2(__nv_bfloat16 a, __nv_bfloat16 b) {
    return (uint32_t)__bfloat16_as_ushort(a) | ((uint32_t)__bfloat16_as_ushort(b) << 16);
}
__device__ __forceinline__ void split2_packed(float a, float b, uint32_t& hi, uint32_t& lo) {
    __nv_bfloat16 ha, la, hb, lb;
    split1(a, ha, la);
    split1(b, hb, lb);
    hi = pack2(ha, hb);
    lo = pack2(la, lb);
}
__device__ __forceinline__ int detect_is64(const void* ei) {
    __shared__ int s_is64;
    if (threadIdx.x == 0) s_is64 = 1;
    __syncthreads();
    if (threadIdx.x < 64) {
        long long v = ((const long long*)ei)[threadIdx.x];
        if (v < 0 || v >= (long long)NNODES) atomicAnd(&s_is64, 0);
    }
    __syncthreads();
    return s_is64;
}

// ---------------- kernel 1: detect + degree count + W fragment-pack + stat reset ----------------
__global__ void deg_wsplit_kernel(const void* ei, int E,
                                  const float* __restrict__ W1,
                                  const float* __restrict__ W2) {
    int is64 = detect_is64(ei);
    int i = blockIdx.x * 256 + threadIdx.x;
    if (i < E) {
        int d = is64 ? (int)((const long long*)ei)[(long long)E + i]
                     : ((const int*)ei)[(long long)E + i];
        atomicAdd(&g_degi[d], 1);
    }
    if (i < 512) g_stat[i] = 0ULL;
    if (i < 16 * 8 * 32) {
        int lane = i & 31, ks = (i >> 5) & 7, nt = i >> 8;
        int g = lane >> 2, tg = lane & 3;
        int n = nt * 8 + g;
        int k = ks * 16 + tg * 2;
        __nv_bfloat16 h0, l0, h1, l1, h2, l2, h3, l3;
        split1(W1[(k + 0) * 128 + n], h0, l0);
        split1(W1[(k + 1) * 128 + n], h1, l1);
        split1(W1[(k + 8) * 128 + n], h2, l2);
        split1(W1[(k + 9) * 128 + n], h3, l3);
        g_w1hp[i] = make_uint2(pack2(h0, h1), pack2(h2, h3));
        g_w1lp[i] = make_uint2(pack2(l0, l1), pack2(l2, l3));
    }
    if (i < 8 * 8 * 32) {
        int lane = i & 31, ks = (i >> 5) & 7, nt = i >> 8;
        int g = lane >> 2, tg = lane & 3;
        int n = nt * 8 + g;
        int k = ks * 16 + tg * 2;
        __nv_bfloat16 h0, l0, h1, l1, h2, l2, h3, l3;
        split1(W2[(k + 0) * 64 + n], h0, l0);
        split1(W2[(k + 1) * 64 + n], h1, l1);
        split1(W2[(k + 8) * 64 + n], h2, l2);
        split1(W2[(k + 9) * 64 + n], h3, l3);
        g_w2hp[i] = make_uint2(pack2(h0, h1), pack2(h2, h3));
        g_w2lp[i] = make_uint2(pack2(l0, l1), pack2(l2, l3));
    }
}

// ---------------- kernel 2: dinv + BN + single-pass scan (decoupled lookback) ----------------
__global__ void __launch_bounds__(256) scan_fused_kernel(int E,
                                  const float* __restrict__ b1,
                                  const float* __restrict__ gamma,
                                  const float* __restrict__ beta,
                                  const float* __restrict__ rmean,
                                  const float* __restrict__ rvar) {
    __shared__ int sm[256];
    __shared__ int s_excl;
    const int bid = blockIdx.x, tid = threadIdx.x;
    int i = bid * 256 + tid;
    int v = 0;
    if (i < NNODES) {
        v = g_degi[i];
        g_degi[i] = 0;
        g_dinv[i] = rsqrtf((float)v + 1.0f);
    }
    if (i < H1DIM) {
        float s = gamma[i] * rsqrtf(rvar[i] + BN_EPS);
        g_bns[i] = s;
        g_bnt[i] = (b1[i] - rmean[i]) * s + beta[i];
    }
    sm[tid] = v;
    __syncthreads();
    for (int off = 1; off < 256; off <<= 1) {
        int t = (tid >= off) ? sm[tid - off] : 0;
        __syncthreads();
        sm[tid] += t;
        __syncthreads();
    }
    int incl = sm[tid];
    int agg = sm[255];

    if (tid == 0) {
        long long excl = 0;
        if (bid == 0) {
            *(volatile unsigned long long*)&g_stat[0] =
                (2ULL << 62) | (unsigned long long)agg;
        } else {
            *(volatile unsigned long long*)&g_stat[bid] =
                (1ULL << 62) | (unsigned long long)agg;
            for (int p = bid - 1; p >= 0;) {
                unsigned long long st;
                do { st = *(volatile unsigned long long*)&g_stat[p]; } while ((st >> 62) == 0);
                excl += (long long)(st & 0x3FFFFFFFFFFFFFFFULL);
                if ((st >> 62) == 2ULL) break;
                p--;
            }
            *(volatile unsigned long long*)&g_stat[bid] =
                (2ULL << 62) | (unsigned long long)(excl + agg);
        }
        s_excl = (int)excl;
    }
    __syncthreads();
    int excl = s_excl;
    if (i < NNODES) {
        int r = excl + incl - v;
        g_rowptr[i] = r;
        g_cursor[i] = r;
    }
    if (bid == NSCAN - 1 && tid == 255) {
        g_rowptr[NNODES] = E;
        g_rowptr[NNODES + 1] = E;
    }
}

// ---------------- kernel 3: permute edges into CSR ----------------
__global__ void permute_kernel(const void* __restrict__ ei, int E) {
    int is64 = detect_is64(ei);
    int e = blockIdx.x * 256 + threadIdx.x;
    if (e >= E) return;
    int s, d;
    if (is64) {
        s = (int)((const long long*)ei)[e];
        d = (int)((const long long*)ei)[(long long)E + e];
    } else {
        s = ((const int*)ei)[e];
        d = ((const int*)ei)[(long long)E + e];
    }
    float nm = g_dinv[s] * g_dinv[d];
    int pos = atomicAdd(&g_cursor[d], 1);
    g_esrc[pos] = s;
    g_enorm[pos] = nm;
}

// ---------------- fused: gather(x) -> MMA1 -> BN/ReLU -> MMA2 -> h2 ----------------
// 256 threads = 8 warps, 64-row tiles, 4 CTAs/SM. All W streams from global (L1-resident).
#define SMF_AHI 0
#define SMF_ALO (64 * PAD)
#define SMF_TOTAL (2 * 64 * PAD * 2)   // 34,816 B

__global__ void __launch_bounds__(256, 4) fused_kernel(const float* __restrict__ x) {
    extern __shared__ __nv_bfloat16 sm[];
    const uint32_t sbase = (uint32_t)__cvta_generic_to_shared(sm);
    const int tid = threadIdx.x, wid = tid >> 5, lid = tid & 31;
    const int row0 = blockIdx.x * 64;

    // ---- gather phase: warp handles 8 local rows as 4 node pairs (unroll-4) ----
    const float4* xr = (const float4*)x;
#pragma unroll 1
    for (int pair = 0; pair < 4; pair++) {
        int rl0 = wid * 8 + pair * 2;
        int n0 = row0 + rl0, n1 = n0 + 1;
        float4 acc0 = make_float4(0.f, 0.f, 0.f, 0.f);
        float4 acc1 = make_float4(0.f, 0.f, 0.f, 0.f);
        int beg0 = 0, end0 = 0, end1 = 0;
        if (n0 < NNODES) {
            beg0 = g_rowptr[n0];
            end0 = g_rowptr[n0 + 1];
            end1 = g_rowptr[n0 + 2];
            float di0 = g_dinv[n0];
            acc0 = xr[(size_t)n0 * 32 + lid];
            acc0.x *= di0 * di0; acc0.y *= di0 * di0;
            acc0.z *= di0 * di0; acc0.w *= di0 * di0;
            if (n1 < NNODES) {
                float di1 = g_dinv[n1];
                acc1 = xr[(size_t)n1 * 32 + lid];
                acc1.x *= di1 * di1; acc1.y *= di1 * di1;
                acc1.z *= di1 * di1; acc1.w *= di1 * di1;
            } else {
                end1 = end0;
            }
        }
        int j = beg0;
        for (; j + 4 <= end1; j += 4) {
            int s0 = g_esrc[j], s1 = g_esrc[j + 1], s2 = g_esrc[j + 2], s3 = g_esrc[j + 3];
            float m0 = g_enorm[j], m1 = g_enorm[j + 1], m2 = g_enorm[j + 2], m3 = g_enorm[j + 3];
            float4 v0 = xr[(size_t)s0 * 32 + lid];
            float4 v1 = xr[(size_t)s1 * 32 + lid];
            float4 v2 = xr[(size_t)s2 * 32 + lid];
            float4 v3 = xr[(size_t)s3 * 32 + lid];
            float4* a0 = (j + 0 < end0) ? &acc0 : &acc1;
            float4* a1 = (j + 1 < end0) ? &acc0 : &acc1;
            float4* a2 = (j + 2 < end0) ? &acc0 : &acc1;
            float4* a3 = (j + 3 < end0) ? &acc0 : &acc1;
            a0->x += v0.x * m0; a0->y += v0.y * m0; a0->z += v0.z * m0; a0->w += v0.w * m0;
            a1->x += v1.x * m1; a1->y += v1.y * m1; a1->z += v1.z * m1; a1->w += v1.w * m1;
            a2->x += v2.x * m2; a2->y += v2.y * m2; a2->z += v2.z * m2; a2->w += v2.w * m2;
            a3->x += v3.x * m3; a3->y += v3.y * m3; a3->z += v3.z * m3; a3->w += v3.w * m3;
        }
        for (; j < end1; j++) {
            int s0 = g_esrc[j];
            float m0 = g_enorm[j];
            float4 v0 = xr[(size_t)s0 * 32 + lid];
            float4* a = (j < end0) ? &acc0 : &acc1;
            a->x += v0.x * m0; a->y += v0.y * m0; a->z += v0.z * m0; a->w += v0.w * m0;
        }
        uint32_t h0a, l0a, h0b, l0b;
        split2_packed(acc0.x, acc0.y, h0a, l0a);
        split2_packed(acc0.z, acc0.w, h0b, l0b);
        *(uint2*)&sm[SMF_AHI + rl0 * PAD + lid * 4] = make_uint2(h0a, h0b);
        *(uint2*)&sm[SMF_ALO + rl0 * PAD + lid * 4] = make_uint2(l0a, l0b);
        uint32_t h1a, l1a, h1b, l1b;
        split2_packed(acc1.x, acc1.y, h1a, l1a);
        split2_packed(acc1.z, acc1.w, h1b, l1b);
        *(uint2*)&sm[SMF_AHI + (rl0 + 1) * PAD + lid * 4] = make_uint2(h1a, h1b);
        *(uint2*)&sm[SMF_ALO + (rl0 + 1) * PAD + lid * 4] = make_uint2(l1a, l1b);
    }
    __syncthreads();

    // warp grid 2x4
    const int wr = wid >> 2, wc = wid & 3;
    const int g = lid >> 2, tg = lid & 3;
    const int ar0 = wr * 32;

    const int m4 = lid >> 3;
    const int arow = (m4 & 1) * 8 + (lid & 7);
    const int acol = (m4 >> 1) * 8;
    const uint32_t offA0 = (uint32_t)(((ar0 + arow) * PAD + acol) * 2);
    const uint32_t offA1 = (uint32_t)(((ar0 + 16 + arow) * PAD + acol) * 2);

    // ---------- MMA1: warp tile 32x32 at (ar0, nc1) ----------
    {
        const int nc1 = wc * 32;
        float acc[2][4][4];
#pragma unroll
        for (int mi = 0; mi < 2; mi++)
#pragma unroll
            for (int ni = 0; ni < 4; ni++)
#pragma unroll
                for (int j = 0; j < 4; j++) acc[mi][ni][j] = 0.f;

#pragma unroll 1
        for (int pass = 0; pass < 3; pass++) {
            uint32_t abase = sbase + 2 * ((pass == 2) ? SMF_ALO : SMF_AHI);
            const uint2* wp = (pass == 1) ? g_w1lp : g_w1hp;
#pragma unroll 1
            for (int ks = 0; ks < 8; ks++) {
                uint32_t kb = (uint32_t)ks * 32;
                uint32_t a0[4], a1[4];
                ldsm_x4(a0[0], a0[1], a0[2], a0[3], abase + offA0 + kb);
                ldsm_x4(a1[0], a1[1], a1[2], a1[3], abase + offA1 + kb);
#pragma unroll
                for (int ni = 0; ni < 4; ni++) {
                    uint2 bf = wp[((wc * 4 + ni) * 8 + ks) * 32 + lid];
                    mma_bf16(acc[0][ni], a0, bf.x, bf.y);
                    mma_bf16(acc[1][ni], a1, bf.x, bf.y);
                }
            }
        }

        __syncthreads();

        // BN + ReLU + split -> overwrite A planes
#pragma unroll
        for (int mi = 0; mi < 2; mi++)
#pragma unroll
            for (int h = 0; h < 2; h++) {
                int rl = ar0 + mi * 16 + h * 8 + g;
#pragma unroll
                for (int ni = 0; ni < 4; ni++) {
                    int c = nc1 + ni * 8 + tg * 2;
                    float2 sc = *(const float2*)&g_bns[c];
                    float2 tc = *(const float2*)&g_bnt[c];
                    float v0 = fmaxf(acc[mi][ni][h * 2] * sc.x + tc.x, 0.f);
                    float v1 = fmaxf(acc[mi][ni][h * 2 + 1] * sc.y + tc.y, 0.f);
                    uint32_t hi, lo;
                    split2_packed(v0, v1, hi, lo);
                    *(uint32_t*)&sm[SMF_AHI + rl * PAD + c] = hi;
                    *(uint32_t*)&sm[SMF_ALO + rl * PAD + c] = lo;
                }
            }
    }
    __syncthreads();

    // ---------- MMA2: warp tile 32x16 at (ar0, nc2) ----------
    {
        const int nc2 = wc * 16;
        float acc[2][2][4];
#pragma unroll
        for (int mi = 0; mi < 2; mi++)
#pragma unroll
            for (int ni = 0; ni < 2; ni++)
#pragma unroll
                for (int j = 0; j < 4; j++) acc[mi][ni][j] = 0.f;

#pragma unroll 1
        for (int pass = 0; pass < 3; pass++) {
            uint32_t abase = sbase + 2 * ((pass == 2) ? SMF_ALO : SMF_AHI);
            const uint2* wp = (pass == 1) ? g_w2lp : g_w2hp;
#pragma unroll 1
            for (int ks = 0; ks < 8; ks++) {
                uint32_t kb = (uint32_t)ks * 32;
                uint32_t a0[4], a1[4];
                ldsm_x4(a0[0], a0[1], a0[2], a0[3], abase + offA0 + kb);
                ldsm_x4(a1[0], a1[1], a1[2], a1[3], abase + offA1 + kb);
#pragma unroll
                for (int ni = 0; ni < 2; ni++) {
                    uint2 bf = wp[((wc * 2 + ni) * 8 + ks) * 32 + lid];
                    mma_bf16(acc[0][ni], a0, bf.x, bf.y);
                    mma_bf16(acc[1][ni], a1, bf.x, bf.y);
                }
            }
        }

#pragma unroll
        for (int mi = 0; mi < 2; mi++)
#pragma unroll
            for (int h = 0; h < 2; h++) {
                int r = row0 + ar0 + mi * 16 + g + h * 8;
                if (r < NNODES) {
#pragma unroll
                    for (int ni = 0; ni < 2; ni++) {
                        int c = nc2 + ni * 8 + tg * 2;
                        *(float2*)&g_h2[(size_t)r * 64 + c] =
                            make_float2(acc[mi][ni][h * 2], acc[mi][ni][h * 2 + 1]);
                    }
                }
            }
    }
}

// ---------------- agg2: half-warp per node (unroll-4) ----------------
__global__ void __launch_bounds__(256) agg2_kernel(const float* __restrict__ b2,
                                                   float* __restrict__ out) {
    int t = blockIdx.x * blockDim.x + threadIdx.x;
    int hw = t >> 4;
    int sub = t & 15;
    if (hw >= NNODES) return;
    int beg = g_rowptr[hw], end = g_rowptr[hw + 1];
    float di = g_dinv[hw];
    float d2 = di * di;
    const float4* h2 = (const float4*)g_h2;
    float4 acc = h2[(size_t)hw * 16 + sub];
    acc.x *= d2; acc.y *= d2; acc.z *= d2; acc.w *= d2;
    int j = beg;
    for (; j + 4 <= end; j += 4) {
        int s0 = g_esrc[j], s1 = g_esrc[j + 1], s2 = g_esrc[j + 2], s3 = g_esrc[j + 3];
        float n0 = g_enorm[j], n1 = g_enorm[j + 1], n2 = g_enorm[j + 2], n3 = g_enorm[j + 3];
        float4 v0 = h2[(size_t)s0 * 16 + sub];
        float4 v1 = h2[(size_t)s1 * 16 + sub];
        float4 v2 = h2[(size_t)s2 * 16 + sub];
        float4 v3 = h2[(size_t)s3 * 16 + sub];
        acc.x += v0.x * n0 + v1.x * n1 + v2.x * n2 + v3.x * n3;
        acc.y += v0.y * n0 + v1.y * n1 + v2.y * n2 + v3.y * n3;
        acc.z += v0.z * n0 + v1.z * n1 + v2.z * n2 + v3.z * n3;
        acc.w += v0.w * n0 + v1.w * n1 + v2.w * n2 + v3.w * n3;
    }
    for (; j < end; j++) {
        int s0 = g_esrc[j];
        float n0 = g_enorm[j];
        float4 v0 = h2[(size_t)s0 * 16 + sub];
        acc.x += v0.x * n0; acc.y += v0.y * n0; acc.z += v0.z * n0; acc.w += v0.w * n0;
    }
    float4 bv = ((const float4*)b2)[sub];
    ((float4*)out)[(size_t)hw * 16 + sub] =
        make_float4(acc.x + bv.x, acc.y + bv.y, acc.z + bv.z, acc.w + bv.w);
}

// ---------------- launch ----------------
extern "C" void kernel_launch(void* const* d_in, const int* in_sizes, int n_in,
                              void* d_out, int out_size) {
    const float* x     = (const float*)d_in[0];
    const void*  ei    = d_in[1];
    const float* W1    = (const float*)d_in[2];
    const float* b1    = (const float*)d_in[3];
    const float* gamma = (const float*)d_in[4];
    const float* beta  = (const float*)d_in[5];
    const float* rmean = (const float*)d_in[6];
    const float* rvar  = (const float*)d_in[7];
    const float* W2    = (const float*)d_in[8];
    const float* b2    = (const float*)d_in[9];
    float* out = (float*)d_out;

    const int E = in_sizes[1] / 2;

    cudaFuncSetAttribute(fused_kernel, cudaFuncAttributeMaxDynamicSharedMemorySize, SMF_TOTAL);

    int eblk = (E + 255) / 256;
    deg_wsplit_kernel<<<eblk, 256>>>(ei, E, W1, W2);
    scan_fused_kernel<<<NSCAN, 256>>>(E, b1, gamma, beta, rmean, rvar);
    permute_kernel<<<eblk, 256>>>(ei, E);

    int gblk = (NNODES + 63) / 64;  // 1563
    fused_kernel<<<gblk, 256, SMF_TOTAL>>>(x);

    {
        long long th = (long long)NNODES * 16;
        agg2_kernel<<<(int)((th + 255) / 256), 256>>>(b2, out);
    }
}

// round 15
// speedup vs baseline: 1.3723x; 1.0447x over previous
#include <cuda_runtime.h>
#include <cuda_bf16.h>
#include <stdint.h>

#define NNODES 100000
#define H1DIM 128
#define H2DIM 64
#define BN_EPS 1e-5f
#define PAD 136
#define EMAX (1 << 20)
#define NSCAN 391   // ceil(NNODES/256)

// ---------------- scratch ----------------
__device__ int   g_degi[NNODES];
__device__ float g_dinv[NNODES];
__device__ int   g_rowptr[NNODES + 2];
__device__ int   g_cursor[NNODES];
__device__ unsigned long long g_stat[512];   // decoupled-lookback state
__device__ int   g_esrc[EMAX];
__device__ float g_enorm[EMAX];
__device__ float g_h2[(size_t)NNODES * H2DIM];
__device__ float g_bns[H1DIM];
__device__ float g_bnt[H1DIM];
// fragment-packed weights: [ntile][ks][lane] -> {b0, b1} (uint2)
__device__ __align__(16) uint2 g_w1hp[16 * 8 * 32];
__device__ __align__(16) uint2 g_w1lp[16 * 8 * 32];
__device__ __align__(16) uint2 g_w2hp[8 * 8 * 32];
__device__ __align__(16) uint2 g_w2lp[8 * 8 * 32];

// ---------------- helpers ----------------
__device__ __forceinline__ void mma_bf16(float* c, const uint32_t* a, uint32_t b0, uint32_t b1) {
    asm volatile("mma.sync.aligned.m16n8k16.row.col.f32.bf16.bf16.f32 "
                 "{%0,%1,%2,%3}, {%4,%5,%6,%7}, {%8,%9}, {%0,%1,%2,%3};"
                 : "+f"(c[0]), "+f"(c[1]), "+f"(c[2]), "+f"(c[3])
                 : "r"(a[0]), "r"(a[1]), "r"(a[2]), "r"(a[3]), "r"(b0), "r"(b1));
}
__device__ __forceinline__ void ldsm_x4(uint32_t& r0, uint32_t& r1, uint32_t& r2, uint32_t& r3,
                                        uint32_t addr) {
    asm volatile("ldmatrix.sync.aligned.m8n8.x4.shared.b16 {%0,%1,%2,%3}, [%4];"
                 : "=r"(r0), "=r"(r1), "=r"(r2), "=r"(r3) : "r"(addr));
}
__device__ __forceinline__ void split1(float v, __nv_bfloat16& hi, __nv_bfloat16& lo) {
    hi = __float2bfloat16_rn(v);
    lo = __float2bfloat16_rn(v - __bfloat162float(hi));
}
__device__ __forceinline__ uint32_t pack2(__nv_bfloat16 a, __nv_bfloat16 b) {
    return (uint32_t)__bfloat16_as_ushort(a) | ((uint32_t)__bfloat16_as_ushort(b) << 16);
}
__device__ __forceinline__ void split2_packed(float a, float b, uint32_t& hi, uint32_t& lo) {
    __nv_bfloat16 ha, la, hb, lb;
    split1(a, ha, la);
    split1(b, hb, lb);
    hi = pack2(ha, hb);
    lo = pack2(la, lb);
}
__device__ __forceinline__ int detect_is64(const void* ei) {
    __shared__ int s_is64;
    if (threadIdx.x == 0) s_is64 = 1;
    __syncthreads();
    if (threadIdx.x < 64) {
        long long v = ((const long long*)ei)[threadIdx.x];
        if (v < 0 || v >= (long long)NNODES) atomicAnd(&s_is64, 0);
    }
    __syncthreads();
    return s_is64;
}

// ---------------- kernel 1: detect + degree count + W fragment-pack + stat reset ----------------
__global__ void deg_wsplit_kernel(const void* ei, int E,
                                  const float* __restrict__ W1,
                                  const float* __restrict__ W2) {
    int is64 = detect_is64(ei);
    int i = blockIdx.x * 256 + threadIdx.x;
    if (i < E) {
        int d = is64 ? (int)((const long long*)ei)[(long long)E + i]
                     : ((const int*)ei)[(long long)E + i];
        atomicAdd(&g_degi[d], 1);
    }
    if (i < 512) g_stat[i] = 0ULL;
    if (i < 16 * 8 * 32) {
        int lane = i & 31, ks = (i >> 5) & 7, nt = i >> 8;
        int g = lane >> 2, tg = lane & 3;
        int n = nt * 8 + g;
        int k = ks * 16 + tg * 2;
        __nv_bfloat16 h0, l0, h1, l1, h2, l2, h3, l3;
        split1(W1[(k + 0) * 128 + n], h0, l0);
        split1(W1[(k + 1) * 128 + n], h1, l1);
        split1(W1[(k + 8) * 128 + n], h2, l2);
        split1(W1[(k + 9) * 128 + n], h3, l3);
        g_w1hp[i] = make_uint2(pack2(h0, h1), pack2(h2, h3));
        g_w1lp[i] = make_uint2(pack2(l0, l1), pack2(l2, l3));
    }
    if (i < 8 * 8 * 32) {
        int lane = i & 31, ks = (i >> 5) & 7, nt = i >> 8;
        int g = lane >> 2, tg = lane & 3;
        int n = nt * 8 + g;
        int k = ks * 16 + tg * 2;
        __nv_bfloat16 h0, l0, h1, l1, h2, l2, h3, l3;
        split1(W2[(k + 0) * 64 + n], h0, l0);
        split1(W2[(k + 1) * 64 + n], h1, l1);
        split1(W2[(k + 8) * 64 + n], h2, l2);
        split1(W2[(k + 9) * 64 + n], h3, l3);
        g_w2hp[i] = make_uint2(pack2(h0, h1), pack2(h2, h3));
        g_w2lp[i] = make_uint2(pack2(l0, l1), pack2(l2, l3));
    }
}

// ---------------- kernel 2: dinv + BN + single-pass scan (decoupled lookback) ----------------
__global__ void __launch_bounds__(256) scan_fused_kernel(int E,
                                  const float* __restrict__ b1,
                                  const float* __restrict__ gamma,
                                  const float* __restrict__ beta,
                                  const float* __restrict__ rmean,
                                  const float* __restrict__ rvar) {
    __shared__ int sm[256];
    __shared__ int s_excl;
    const int bid = blockIdx.x, tid = threadIdx.x;
    int i = bid * 256 + tid;
    int v = 0;
    if (i < NNODES) {
        v = g_degi[i];
        g_degi[i] = 0;
        g_dinv[i] = rsqrtf((float)v + 1.0f);
    }
    if (i < H1DIM) {
        float s = gamma[i] * rsqrtf(rvar[i] + BN_EPS);
        g_bns[i] = s;
        g_bnt[i] = (b1[i] - rmean[i]) * s + beta[i];
    }
    sm[tid] = v;
    __syncthreads();
    for (int off = 1; off < 256; off <<= 1) {
        int t = (tid >= off) ? sm[tid - off] : 0;
        __syncthreads();
        sm[tid] += t;
        __syncthreads();
    }
    int incl = sm[tid];
    int agg = sm[255];

    if (tid == 0) {
        long long excl = 0;
        if (bid == 0) {
            *(volatile unsigned long long*)&g_stat[0] =
                (2ULL << 62) | (unsigned long long)agg;
        } else {
            *(volatile unsigned long long*)&g_stat[bid] =
                (1ULL << 62) | (unsigned long long)agg;
            for (int p = bid - 1; p >= 0;) {
                unsigned long long st;
                do { st = *(volatile unsigned long long*)&g_stat[p]; } while ((st >> 62) == 0);
                excl += (long long)(st & 0x3FFFFFFFFFFFFFFFULL);
                if ((st >> 62) == 2ULL) break;
                p--;
            }
            *(volatile unsigned long long*)&g_stat[bid] =
                (2ULL << 62) | (unsigned long long)(excl + agg);
        }
        s_excl = (int)excl;
    }
    __syncthreads();
    int excl = s_excl;
    if (i < NNODES) {
        int r = excl + incl - v;
        g_rowptr[i] = r;
        g_cursor[i] = r;
    }
    if (bid == NSCAN - 1 && tid == 255) {
        g_rowptr[NNODES] = E;
        g_rowptr[NNODES + 1] = E;
    }
}

// ---------------- kernel 3: permute edges into CSR ----------------
__global__ void permute_kernel(const void* __restrict__ ei, int E) {
    int is64 = detect_is64(ei);
    int e = blockIdx.x * 256 + threadIdx.x;
    if (e >= E) return;
    int s, d;
    if (is64) {
        s = (int)((const long long*)ei)[e];
        d = (int)((const long long*)ei)[(long long)E + e];
    } else {
        s = ((const int*)ei)[e];
        d = ((const int*)ei)[(long long)E + e];
    }
    float nm = g_dinv[s] * g_dinv[d];
    int pos = atomicAdd(&g_cursor[d], 1);
    g_esrc[pos] = s;
    g_enorm[pos] = nm;
}

// ---------------- fused: gather(x) -> MMA1 -> BN/ReLU -> MMA2 -> h2 ----------------
// 256 threads = 8 warps, 64-row tiles, 4 CTAs/SM. Single-pass compensated MMA loops.
#define SMF_AHI 0
#define SMF_ALO (64 * PAD)
#define SMF_TOTAL (2 * 64 * PAD * 2)   // 34,816 B

__global__ void __launch_bounds__(256, 4) fused_kernel(const float* __restrict__ x) {
    extern __shared__ __nv_bfloat16 sm[];
    const uint32_t sbase = (uint32_t)__cvta_generic_to_shared(sm);
    const int tid = threadIdx.x, wid = tid >> 5, lid = tid & 31;
    const int row0 = blockIdx.x * 64;

    // ---- gather phase: warp handles 8 local rows as 4 node pairs (unroll-4) ----
    const float4* xr = (const float4*)x;
#pragma unroll 1
    for (int pair = 0; pair < 4; pair++) {
        int rl0 = wid * 8 + pair * 2;
        int n0 = row0 + rl0, n1 = n0 + 1;
        float4 acc0 = make_float4(0.f, 0.f, 0.f, 0.f);
        float4 acc1 = make_float4(0.f, 0.f, 0.f, 0.f);
        int beg0 = 0, end0 = 0, end1 = 0;
        if (n0 < NNODES) {
            beg0 = g_rowptr[n0];
            end0 = g_rowptr[n0 + 1];
            end1 = g_rowptr[n0 + 2];
            float di0 = g_dinv[n0];
            acc0 = xr[(size_t)n0 * 32 + lid];
            acc0.x *= di0 * di0; acc0.y *= di0 * di0;
            acc0.z *= di0 * di0; acc0.w *= di0 * di0;
            if (n1 < NNODES) {
                float di1 = g_dinv[n1];
                acc1 = xr[(size_t)n1 * 32 + lid];
                acc1.x *= di1 * di1; acc1.y *= di1 * di1;
                acc1.z *= di1 * di1; acc1.w *= di1 * di1;
            } else {
                end1 = end0;
            }
        }
        int j = beg0;
        for (; j + 4 <= end1; j += 4) {
            int s0 = g_esrc[j], s1 = g_esrc[j + 1], s2 = g_esrc[j + 2], s3 = g_esrc[j + 3];
            float m0 = g_enorm[j], m1 = g_enorm[j + 1], m2 = g_enorm[j + 2], m3 = g_enorm[j + 3];
            float4 v0 = xr[(size_t)s0 * 32 + lid];
            float4 v1 = xr[(size_t)s1 * 32 + lid];
            float4 v2 = xr[(size_t)s2 * 32 + lid];
            float4 v3 = xr[(size_t)s3 * 32 + lid];
            float4* a0 = (j + 0 < end0) ? &acc0 : &acc1;
            float4* a1 = (j + 1 < end0) ? &acc0 : &acc1;
            float4* a2 = (j + 2 < end0) ? &acc0 : &acc1;
            float4* a3 = (j + 3 < end0) ? &acc0 : &acc1;
            a0->x += v0.x * m0; a0->y += v0.y * m0; a0->z += v0.z * m0; a0->w += v0.w * m0;
            a1->x += v1.x * m1; a1->y += v1.y * m1; a1->z += v1.z * m1; a1->w += v1.w * m1;
            a2->x += v2.x * m2; a2->y += v2.y * m2; a2->z += v2.z * m2; a2->w += v2.w * m2;
            a3->x += v3.x * m3; a3->y += v3.y * m3; a3->z += v3.z * m3; a3->w += v3.w * m3;
        }
        for (; j < end1; j++) {
            int s0 = g_esrc[j];
            float m0 = g_enorm[j];
            float4 v0 = xr[(size_t)s0 * 32 + lid];
            float4* a = (j < end0) ? &acc0 : &acc1;
            a->x += v0.x * m0; a->y += v0.y * m0; a->z += v0.z * m0; a->w += v0.w * m0;
        }
        uint32_t h0a, l0a, h0b, l0b;
        split2_packed(acc0.x, acc0.y, h0a, l0a);
        split2_packed(acc0.z, acc0.w, h0b, l0b);
        *(uint2*)&sm[SMF_AHI + rl0 * PAD + lid * 4] = make_uint2(h0a, h0b);
        *(uint2*)&sm[SMF_ALO + rl0 * PAD + lid * 4] = make_uint2(l0a, l0b);
        uint32_t h1a, l1a, h1b, l1b;
        split2_packed(acc1.x, acc1.y, h1a, l1a);
        split2_packed(acc1.z, acc1.w, h1b, l1b);
        *(uint2*)&sm[SMF_AHI + (rl0 + 1) * PAD + lid * 4] = make_uint2(h1a, h1b);
        *(uint2*)&sm[SMF_ALO + (rl0 + 1) * PAD + lid * 4] = make_uint2(l1a, l1b);
    }
    __syncthreads();

    // warp grid 2x4
    const int wr = wid >> 2, wc = wid & 3;
    const int g = lid >> 2, tg = lid & 3;
    const int ar0 = wr * 32;

    const int m4 = lid >> 3;
    const int arow = (m4 & 1) * 8 + (lid & 7);
    const int acol = (m4 >> 1) * 8;
    const uint32_t offA0 = (uint32_t)(((ar0 + arow) * PAD + acol) * 2);
    const uint32_t offA1 = (uint32_t)(((ar0 + 16 + arow) * PAD + acol) * 2);
    const uint32_t aHI = sbase + 2 * SMF_AHI;
    const uint32_t aLO = sbase + 2 * SMF_ALO;

    // ---------- MMA1: warp tile 32x32 at (ar0, nc1), single-pass compensated ----------
    {
        const int nc1 = wc * 32;
        float acc[2][4][4];
#pragma unroll
        for (int mi = 0; mi < 2; mi++)
#pragma unroll
            for (int ni = 0; ni < 4; ni++)
#pragma unroll
                for (int j = 0; j < 4; j++) acc[mi][ni][j] = 0.f;

        const uint2* whB = &g_w1hp[(wc * 4) * 8 * 32 + lid];
        const uint2* wlB = &g_w1lp[(wc * 4) * 8 * 32 + lid];
#pragma unroll 1
        for (int ks = 0; ks < 8; ks++) {
            uint32_t kb = (uint32_t)ks * 32;
            uint32_t a0h[4], a1h[4], a0l[4], a1l[4];
            ldsm_x4(a0h[0], a0h[1], a0h[2], a0h[3], aHI + offA0 + kb);
            ldsm_x4(a1h[0], a1h[1], a1h[2], a1h[3], aHI + offA1 + kb);
            ldsm_x4(a0l[0], a0l[1], a0l[2], a0l[3], aLO + offA0 + kb);
            ldsm_x4(a1l[0], a1l[1], a1l[2], a1l[3], aLO + offA1 + kb);
#pragma unroll
            for (int ni = 0; ni < 4; ni++) {
                uint2 bh = whB[(ni * 8 + ks) * 32];
                uint2 bl = wlB[(ni * 8 + ks) * 32];
                mma_bf16(acc[0][ni], a0h, bh.x, bh.y);
                mma_bf16(acc[1][ni], a1h, bh.x, bh.y);
                mma_bf16(acc[0][ni], a0h, bl.x, bl.y);
                mma_bf16(acc[1][ni], a1h, bl.x, bl.y);
                mma_bf16(acc[0][ni], a0l, bh.x, bh.y);
                mma_bf16(acc[1][ni], a1l, bh.x, bh.y);
            }
        }

        __syncthreads();

        // BN + ReLU + split -> overwrite A planes
#pragma unroll
        for (int mi = 0; mi < 2; mi++)
#pragma unroll
            for (int h = 0; h < 2; h++) {
                int rl = ar0 + mi * 16 + h * 8 + g;
#pragma unroll
                for (int ni = 0; ni < 4; ni++) {
                    int c = nc1 + ni * 8 + tg * 2;
                    float2 sc = *(const float2*)&g_bns[c];
                    float2 tc = *(const float2*)&g_bnt[c];
                    float v0 = fmaxf(acc[mi][ni][h * 2] * sc.x + tc.x, 0.f);
                    float v1 = fmaxf(acc[mi][ni][h * 2 + 1] * sc.y + tc.y, 0.f);
                    uint32_t hi, lo;
                    split2_packed(v0, v1, hi, lo);
                    *(uint32_t*)&sm[SMF_AHI + rl * PAD + c] = hi;
                    *(uint32_t*)&sm[SMF_ALO + rl * PAD + c] = lo;
                }
            }
    }
    __syncthreads();

    // ---------- MMA2: warp tile 32x16 at (ar0, nc2), single-pass compensated ----------
    {
        const int nc2 = wc * 16;
        float acc[2][2][4];
#pragma unroll
        for (int mi = 0; mi < 2; mi++)
#pragma unroll
            for (int ni = 0; ni < 2; ni++)
#pragma unroll
                for (int j = 0; j < 4; j++) acc[mi][ni][j] = 0.f;

        const uint2* whB = &g_w2hp[(wc * 2) * 8 * 32 + lid];
        const uint2* wlB = &g_w2lp[(wc * 2) * 8 * 32 + lid];
#pragma unroll 1
        for (int ks = 0; ks < 8; ks++) {
            uint32_t kb = (uint32_t)ks * 32;
            uint32_t a0h[4], a1h[4], a0l[4], a1l[4];
            ldsm_x4(a0h[0], a0h[1], a0h[2], a0h[3], aHI + offA0 + kb);
            ldsm_x4(a1h[0], a1h[1], a1h[2], a1h[3], aHI + offA1 + kb);
            ldsm_x4(a0l[0], a0l[1], a0l[2], a0l[3], aLO + offA0 + kb);
            ldsm_x4(a1l[0], a1l[1], a1l[2], a1l[3], aLO + offA1 + kb);
#pragma unroll
            for (int ni = 0; ni < 2; ni++) {
                uint2 bh = whB[(ni * 8 + ks) * 32];
                uint2 bl = wlB[(ni * 8 + ks) * 32];
                mma_bf16(acc[0][ni], a0h, bh.x, bh.y);
                mma_bf16(acc[1][ni], a1h, bh.x, bh.y);
                mma_bf16(acc[0][ni], a0h, bl.x, bl.y);
                mma_bf16(acc[1][ni], a1h, bl.x, bl.y);
                mma_bf16(acc[0][ni], a0l, bh.x, bh.y);
                mma_bf16(acc[1][ni], a1l, bh.x, bh.y);
            }
        }

#pragma unroll
        for (int mi = 0; mi < 2; mi++)
#pragma unroll
            for (int h = 0; h < 2; h++) {
                int r = row0 + ar0 + mi * 16 + g + h * 8;
                if (r < NNODES) {
#pragma unroll
                    for (int ni = 0; ni < 2; ni++) {
                        int c = nc2 + ni * 8 + tg * 2;
                        *(float2*)&g_h2[(size_t)r * 64 + c] =
                            make_float2(acc[mi][ni][h * 2], acc[mi][ni][h * 2 + 1]);
                    }
                }
            }
    }
}

// ---------------- agg2: half-warp per node (unroll-4) ----------------
__global__ void __launch_bounds__(256) agg2_kernel(const float* __restrict__ b2,
                                                   float* __restrict__ out) {
    int t = blockIdx.x * blockDim.x + threadIdx.x;
    int hw = t >> 4;
    int sub = t & 15;
    if (hw >= NNODES) return;
    int beg = g_rowptr[hw], end = g_rowptr[hw + 1];
    float di = g_dinv[hw];
    float d2 = di * di;
    const float4* h2 = (const float4*)g_h2;
    float4 acc = h2[(size_t)hw * 16 + sub];
    acc.x *= d2; acc.y *= d2; acc.z *= d2; acc.w *= d2;
    int j = beg;
    for (; j + 4 <= end; j += 4) {
        int s0 = g_esrc[j], s1 = g_esrc[j + 1], s2 = g_esrc[j + 2], s3 = g_esrc[j + 3];
        float n0 = g_enorm[j], n1 = g_enorm[j + 1], n2 = g_enorm[j + 2], n3 = g_enorm[j + 3];
        float4 v0 = h2[(size_t)s0 * 16 + sub];
        float4 v1 = h2[(size_t)s1 * 16 + sub];
        float4 v2 = h2[(size_t)s2 * 16 + sub];
        float4 v3 = h2[(size_t)s3 * 16 + sub];
        acc.x += v0.x * n0 + v1.x * n1 + v2.x * n2 + v3.x * n3;
        acc.y += v0.y * n0 + v1.y * n1 + v2.y * n2 + v3.y * n3;
        acc.z += v0.z * n0 + v1.z * n1 + v2.z * n2 + v3.z * n3;
        acc.w += v0.w * n0 + v1.w * n1 + v2.w * n2 + v3.w * n3;
    }
    for (; j < end; j++) {
        int s0 = g_esrc[j];
        float n0 = g_enorm[j];
        float4 v0 = h2[(size_t)s0 * 16 + sub];
        acc.x += v0.x * n0; acc.y += v0.y * n0; acc.z += v0.z * n0; acc.w += v0.w * n0;
    }
    float4 bv = ((const float4*)b2)[sub];
    ((float4*)out)[(size_t)hw * 16 + sub] =
        make_float4(acc.x + bv.x, acc.y + bv.y, acc.z + bv.z, acc.w + bv.w);
}

// ---------------- launch ----------------
extern "C" void kernel_launch(void* const* d_in, const int* in_sizes, int n_in,
                              void* d_out, int out_size) {
    const float* x     = (const float*)d_in[0];
    const void*  ei    = d_in[1];
    const float* W1    = (const float*)d_in[2];
    const float* b1    = (const float*)d_in[3];
    const float* gamma = (const float*)d_in[4];
    const float* beta  = (const float*)d_in[5];
    const float* rmean = (const float*)d_in[6];
    const float* rvar  = (const float*)d_in[7];
    const float* W2    = (const float*)d_in[8];
    const float* b2    = (const float*)d_in[9];
    float* out = (float*)d_out;

    const int E = in_sizes[1] / 2;

    cudaFuncSetAttribute(fused_kernel, cudaFuncAttributeMaxDynamicSharedMemorySize, SMF_TOTAL);

    int eblk = (E + 255) / 256;
    deg_wsplit_kernel<<<eblk, 256>>>(ei, E, W1, W2);
    scan_fused_kernel<<<NSCAN, 256>>>(E, b1, gamma, beta, rmean, rvar);
    permute_kernel<<<eblk, 256>>>(ei, E);

    int gblk = (NNODES + 63) / 64;  // 1563
    fused_kernel<<<gblk, 256, SMF_TOTAL>>>(x);

    {
        long long th = (long long)NNODES * 16;
        agg2_kernel<<<(int)((th + 255) / 256), 256>>>(b2, out);
    }
}